// round 3
// baseline (speedup 1.0000x reference)
#include <cuda_runtime.h>
#include <math.h>

// ---------------- scratch (device globals; no allocation allowed) ----------------
__device__ float g_c1[24*32*32*32];   // conv1 out [img][32][32][32]
__device__ float g_c2[24*48*16*16];   // conv2 out [img][48][16][16]
__device__ float g_c3[24*64*8*8];     // conv3 out [img][64][8][8]
__device__ float g_logits[24*64];
__device__ float g_u[24*64*128];      // u[img][p][n]
__device__ float g_v[24*64*128];      // v[img][q][n] (includes bg1)
__device__ float g_score[144];        // score[b][j][i]

// ---------------- conv1: 3->32, 64x64 -> 32x32, stride 2, pad (0,1) ----------------
__global__ void conv1_k(const float* __restrict__ sx, const float* __restrict__ qx,
                        const float* __restrict__ w, const float* __restrict__ bias) {
    int o = blockIdx.x * 256 + threadIdx.x;
    if (o >= 24*32*32*32) return;
    int x = o & 31, y = (o >> 5) & 31, ch = (o >> 10) & 31, img = o >> 15;
    int b = img / 6, s = img - b * 6;
    const float* base = (s < 5) ? sx + (size_t)((b*5 + s)*3) * 4096
                                : qx + (size_t)(b*3) * 4096;
    float acc = bias[ch];
    #pragma unroll
    for (int c = 0; c < 3; c++) {
        const float* in = base + c * 4096;
        const float* wp = w + (ch*3 + c) * 9;
        #pragma unroll
        for (int kh = 0; kh < 3; kh++) {
            int iy = 2*y + kh; if (iy >= 64) continue;
            #pragma unroll
            for (int kw = 0; kw < 3; kw++) {
                int ix = 2*x + kw; if (ix >= 64) continue;
                acc += in[iy*64 + ix] * wp[kh*3 + kw];
            }
        }
    }
    g_c1[o] = fmaxf(acc, 0.f);
}

// ---------------- conv2: 32->48, 32x32 -> 16x16 ----------------
__global__ void conv2_k(const float* __restrict__ w, const float* __restrict__ bias) {
    int o = blockIdx.x * 256 + threadIdx.x;
    if (o >= 24*48*16*16) return;
    int x = o & 15, y = (o >> 4) & 15;
    int t = o >> 8; int ch = t % 48; int img = t / 48;
    float acc = bias[ch];
    const float* inb = g_c1 + (size_t)img * 32768;
    const float* wb  = w + ch * 32 * 9;
    for (int c = 0; c < 32; c++) {
        const float* in = inb + c * 1024;
        const float* wp = wb + c * 9;
        #pragma unroll
        for (int kh = 0; kh < 3; kh++) {
            int iy = 2*y + kh; if (iy >= 32) continue;
            #pragma unroll
            for (int kw = 0; kw < 3; kw++) {
                int ix = 2*x + kw; if (ix >= 32) continue;
                acc += in[iy*32 + ix] * wp[kh*3 + kw];
            }
        }
    }
    g_c2[o] = fmaxf(acc, 0.f);
}

// ---------------- conv3: 48->64, 16x16 -> 8x8 ----------------
__global__ void conv3_k(const float* __restrict__ w, const float* __restrict__ bias) {
    int o = blockIdx.x * 256 + threadIdx.x;
    if (o >= 24*64*8*8) return;
    int x = o & 7, y = (o >> 3) & 7, ch = (o >> 6) & 63, img = o >> 12;
    float acc = bias[ch];
    const float* inb = g_c2 + (size_t)img * 12288;
    const float* wb  = w + ch * 48 * 9;
    for (int c = 0; c < 48; c++) {
        const float* in = inb + c * 256;
        const float* wp = wb + c * 9;
        #pragma unroll
        for (int kh = 0; kh < 3; kh++) {
            int iy = 2*y + kh; if (iy >= 16) continue;
            #pragma unroll
            for (int kw = 0; kw < 3; kw++) {
                int ix = 2*x + kw; if (ix >= 16) continue;
                acc += in[iy*16 + ix] * wp[kh*3 + kw];
            }
        }
    }
    g_c3[o] = fmaxf(acc, 0.f);
}

// ---------------- mean pool + logits: one block per image, 64 threads ----------------
__global__ void poollog_k(const float* __restrict__ Wlog, const float* __restrict__ blog) {
    __shared__ float pooled[64];
    int img = blockIdx.x, c = threadIdx.x;
    const float* fp = g_c3 + (size_t)img * 4096 + c * 64;
    float s = 0.f;
    for (int p = 0; p < 64; p++) s += fp[p];
    pooled[c] = s * (1.f / 64.f);
    __syncthreads();
    int n = threadIdx.x;
    float l = blog[n];
    for (int cc = 0; cc < 64; cc++) l += pooled[cc] * Wlog[cc*64 + n];
    g_logits[img*64 + n] = l;
}

// ---------------- u / v projections: one block per (img, p), 128 threads ----------------
__global__ void uv_k(const float* __restrict__ Wg1, const float* __restrict__ bg1) {
    __shared__ float a[66];
    int img = blockIdx.x >> 6;
    int p   = blockIdx.x & 63;
    int tid = threadIdx.x;
    if (tid < 64) a[tid] = g_c3[(size_t)img*4096 + tid*64 + p];
    if (tid == 64) a[64] = (float)(p >> 3) * 0.125f;   // ii[py]
    if (tid == 65) a[65] = (float)(p & 7)  * 0.125f;   // ii[px]
    __syncthreads();
    int n = tid; // 128
    float uacc = 0.f, vacc = bg1[n];
    for (int c = 0; c < 66; c++) {
        float av = a[c];
        uacc = fmaf(av, Wg1[c*128 + n],        uacc);
        vacc = fmaf(av, Wg1[(66 + c)*128 + n], vacc);
    }
    size_t off = (size_t)img * 8192 + p * 128 + n;
    g_u[off] = uacc;
    g_v[off] = vacc;
}

// ---------------- pair kernel: the 9.66 GFLOP core ----------------
// One CTA per (b,j,i). smem: U[64][128], Vt[128][64], Wt[64][128], accT[64][256], bg2[64]
__global__ void __launch_bounds__(256, 1) pair_k(
    const float* __restrict__ Wg2, const float* __restrict__ bg2,
    const float* __restrict__ Wf1, const float* __restrict__ bf1,
    const float* __restrict__ Wf2, const float* __restrict__ bf2) {
    extern __shared__ float sm[];
    float* U    = sm;               // 8192
    float* Vt   = sm + 8192;        // 8192  Vt[k][q]
    float* Wt   = sm + 16384;       // 8192  Wt[n][k]
    float* accT = sm + 24576;       // 16384 accT[n][tid]
    float* bg2s = sm + 40960;       // 64

    int tid = threadIdx.x;
    int blk = blockIdx.x;
    int b = blk / 36; int r = blk - b*36; int j = r / 6; int i = r - j*6;
    const float* up = g_u + (size_t)(b*6 + i) * 8192;
    const float* vp = g_v + (size_t)(b*6 + j) * 8192;

    for (int idx = tid; idx < 8192; idx += 256) {
        U[idx] = up[idx];
        int q = idx >> 7, k = idx & 127;
        Vt[k*64 + q] = vp[idx];
        int kk = idx >> 6, n = idx & 63;
        Wt[n*128 + kk] = Wg2[idx];
    }
    for (int idx = tid; idx < 16384; idx += 256) accT[idx] = 0.f;
    if (tid < 64) bg2s[tid] = bg2[tid];
    __syncthreads();

    int warp = tid >> 5, lane = tid & 31;
    for (int p = warp; p < 64; p += 8) {
        const float4* Up = (const float4*)(U + p*128);
        for (int qh = 0; qh < 2; ++qh) {
            int q = qh*32 + lane;
            float h[128];
            #pragma unroll
            for (int k4 = 0; k4 < 32; k4++) {
                float4 uu = Up[k4];
                h[4*k4+0] = fmaxf(uu.x + Vt[(4*k4+0)*64 + q], 0.f);
                h[4*k4+1] = fmaxf(uu.y + Vt[(4*k4+1)*64 + q], 0.f);
                h[4*k4+2] = fmaxf(uu.z + Vt[(4*k4+2)*64 + q], 0.f);
                h[4*k4+3] = fmaxf(uu.w + Vt[(4*k4+3)*64 + q], 0.f);
            }
            #pragma unroll 2
            for (int n = 0; n < 64; n++) {
                const float4* Wp = (const float4*)(Wt + n*128);
                float s0 = bg2s[n], s1 = 0.f, s2 = 0.f, s3 = 0.f;
                #pragma unroll
                for (int k4 = 0; k4 < 32; k4++) {
                    float4 w = Wp[k4];
                    s0 = fmaf(h[4*k4+0], w.x, s0);
                    s1 = fmaf(h[4*k4+1], w.y, s1);
                    s2 = fmaf(h[4*k4+2], w.z, s2);
                    s3 = fmaf(h[4*k4+3], w.w, s3);
                }
                float sv = (s0 + s1) + (s2 + s3);
                accT[n*256 + tid] += fmaxf(sv, 0.f);
            }
        }
    }
    __syncthreads();

    // reduce accT -> x_f[64] (reuse U)
    if (tid < 64) {
        float s = 0.f;
        const float* ap = accT + tid*256;
        for (int t = 0; t < 256; t++) s += ap[t];
        U[tid] = s;
    }
    __syncthreads();
    if (tid < 16) {
        float s = bf1[tid];
        for (int c = 0; c < 64; c++) s = fmaf(U[c], Wf1[c*16 + tid], s);
        Vt[tid] = fmaxf(s, 0.f);
    }
    __syncthreads();
    if (tid == 0) {
        float s = bf2[0];
        for (int t = 0; t < 16; t++) s = fmaf(Vt[t], Wf2[t], s);
        g_score[blk] = 1.f / (1.f + __expf(-s));
    }
}

// ---------------- final losses: single block ----------------
__global__ void final_k(const int* __restrict__ sy, const int* __restrict__ qy,
                        float* __restrict__ out) {
    __shared__ float sP[144], sY[144], scls[24];
    __shared__ int slab[24];
    int tid = threadIdx.x;
    if (tid < 144) sP[tid] = g_score[tid];
    if (tid < 24) {
        int b = tid / 6, s = tid - b*6;
        slab[tid] = (s < 5) ? sy[b*5 + s] : qy[b];
    }
    __syncthreads();
    if (tid < 24) {
        const float* row = g_logits + tid*64;
        float m = row[0];
        for (int n = 1; n < 64; n++) m = fmaxf(m, row[n]);
        float se = 0.f;
        for (int n = 0; n < 64; n++) se += __expf(row[n] - m);
        float lse = m + __logf(se);
        scls[tid] = -(row[slab[tid]] - lse);
    }
    if (tid < 144) {
        int b = tid / 36, r = tid - b*36; int jj = r / 6, ii = r - jj*6;
        sY[tid] = (slab[b*6 + jj] == slab[b*6 + ii]) ? 1.f : 0.f;
    }
    __syncthreads();
    if (tid == 0) {
        float cls = 0.f;
        for (int r2 = 0; r2 < 24; r2++) cls += scls[r2];
        cls /= 24.f;
        float euc = 0.f;
        for (int t = 0; t < 144; t++) { float d = sP[t] - sY[t]; euc += d*d; }
        euc /= 144.f;
        float syml = 0.f;
        for (int b2 = 0; b2 < 4; b2++) {
            float s2 = 0.f, a2 = 0.f;
            for (int jj = 0; jj < 6; jj++)
                for (int ii = 0; ii < 6; ii++) {
                    float pa = sP[b2*36 + jj*6 + ii];
                    float pb = sP[b2*36 + ii*6 + jj];
                    float sv = 0.5f*(pa + pb), av = 0.5f*(pa - pb);
                    s2 += sv*sv; a2 += av*av;
                }
            float sn = sqrtf(s2), an = sqrtf(a2);
            syml += (sn - an) / (sn + an);
        }
        syml *= 0.25f;
        out[0] = cls;
        out[1] = euc - 0.1f * syml;
        out[2] = syml;
    }
}

// ---------------- launch ----------------
extern "C" void kernel_launch(void* const* d_in, const int* in_sizes, int n_in,
                              void* d_out, int out_size) {
    const float* sx   = (const float*)d_in[0];
    const int*   sy   = (const int*)  d_in[1];
    const float* qx   = (const float*)d_in[2];
    const int*   qy   = (const int*)  d_in[3];
    const float* k1   = (const float*)d_in[4];
    const float* bc1  = (const float*)d_in[5];
    const float* k2   = (const float*)d_in[6];
    const float* bc2  = (const float*)d_in[7];
    const float* k3   = (const float*)d_in[8];
    const float* bc3  = (const float*)d_in[9];
    const float* Wlog = (const float*)d_in[10];
    const float* blog = (const float*)d_in[11];
    const float* Wg1  = (const float*)d_in[12];
    const float* bg1  = (const float*)d_in[13];
    const float* Wg2  = (const float*)d_in[14];
    const float* bg2  = (const float*)d_in[15];
    const float* Wf1  = (const float*)d_in[16];
    const float* bf1  = (const float*)d_in[17];
    const float* Wf2  = (const float*)d_in[18];
    const float* bf2  = (const float*)d_in[19];
    float* out = (float*)d_out;

    const int pair_smem = (8192*3 + 16384 + 64) * sizeof(float); // 164096 B
    cudaFuncSetAttribute(pair_k, cudaFuncAttributeMaxDynamicSharedMemorySize, pair_smem);

    conv1_k<<<3072, 256>>>(sx, qx, k1, bc1);
    conv2_k<<<1152, 256>>>(k2, bc2);
    conv3_k<<< 384, 256>>>(k3, bc3);
    poollog_k<<<24, 64>>>(Wlog, blog);
    uv_k<<<1536, 128>>>(Wg1, bg1);
    pair_k<<<144, 256, pair_smem>>>(Wg2, bg2, Wf1, bf1, Wf2, bf2);
    final_k<<<1, 160>>>(sy, qy, out);
}

// round 5
// speedup vs baseline: 1.0278x; 1.0278x over previous
#include <cuda_runtime.h>
#include <math.h>

// ---------------- scratch (device globals; no allocation allowed) ----------------
__device__ float g_c1[24*32*32*32];   // conv1 out [img][32][32][32]
__device__ float g_c2[24*48*16*16];   // conv2 out [img][48][16][16]
__device__ float g_c3[24*64*8*8];     // conv3 out [img][64][8][8]
__device__ float g_logits[24*64];
__device__ float g_u[24*64*128];      // u[img][p][n]
__device__ float g_v[24*64*128];      // v[img][q][n] (includes bg1)
__device__ float g_score[144];        // score[b][j][i]

// ---------------- f32x2 packed helpers (sm_103a FFMA2 path) ----------------
__device__ __forceinline__ unsigned long long pack2(float lo, float hi) {
    unsigned long long r;
    asm("mov.b64 %0, {%1, %2};" : "=l"(r) : "f"(lo), "f"(hi));
    return r;
}
__device__ __forceinline__ void unpack2(unsigned long long v, float& lo, float& hi) {
    asm("mov.b64 {%0, %1}, %2;" : "=f"(lo), "=f"(hi) : "l"(v));
}
__device__ __forceinline__ unsigned long long fma2(unsigned long long a,
                                                   unsigned long long b,
                                                   unsigned long long c) {
    unsigned long long d;
    asm("fma.rn.f32x2 %0, %1, %2, %3;" : "=l"(d) : "l"(a), "l"(b), "l"(c));
    return d;
}

// ---------------- conv1: 3->32, 64x64 -> 32x32, stride 2, pad (0,1) ----------------
__global__ void conv1_k(const float* __restrict__ sx, const float* __restrict__ qx,
                        const float* __restrict__ w, const float* __restrict__ bias) {
    int o = blockIdx.x * 256 + threadIdx.x;
    if (o >= 24*32*32*32) return;
    int x = o & 31, y = (o >> 5) & 31, ch = (o >> 10) & 31, img = o >> 15;
    int b = img / 6, s = img - b * 6;
    const float* base = (s < 5) ? sx + (size_t)((b*5 + s)*3) * 4096
                                : qx + (size_t)(b*3) * 4096;
    float acc = bias[ch];
    #pragma unroll
    for (int c = 0; c < 3; c++) {
        const float* in = base + c * 4096;
        const float* wp = w + (ch*3 + c) * 9;
        #pragma unroll
        for (int kh = 0; kh < 3; kh++) {
            int iy = 2*y + kh; if (iy >= 64) continue;
            #pragma unroll
            for (int kw = 0; kw < 3; kw++) {
                int ix = 2*x + kw; if (ix >= 64) continue;
                acc += in[iy*64 + ix] * wp[kh*3 + kw];
            }
        }
    }
    g_c1[o] = fmaxf(acc, 0.f);
}

// ---------------- conv2: 32->48, 32x32 -> 16x16 ----------------
__global__ void conv2_k(const float* __restrict__ w, const float* __restrict__ bias) {
    int o = blockIdx.x * 256 + threadIdx.x;
    if (o >= 24*48*16*16) return;
    int x = o & 15, y = (o >> 4) & 15;
    int t = o >> 8; int ch = t % 48; int img = t / 48;
    float acc = bias[ch];
    const float* inb = g_c1 + (size_t)img * 32768;
    const float* wb  = w + ch * 32 * 9;
    for (int c = 0; c < 32; c++) {
        const float* in = inb + c * 1024;
        const float* wp = wb + c * 9;
        #pragma unroll
        for (int kh = 0; kh < 3; kh++) {
            int iy = 2*y + kh; if (iy >= 32) continue;
            #pragma unroll
            for (int kw = 0; kw < 3; kw++) {
                int ix = 2*x + kw; if (ix >= 32) continue;
                acc += in[iy*32 + ix] * wp[kh*3 + kw];
            }
        }
    }
    g_c2[o] = fmaxf(acc, 0.f);
}

// ---------------- conv3: 48->64, 16x16 -> 8x8 ----------------
__global__ void conv3_k(const float* __restrict__ w, const float* __restrict__ bias) {
    int o = blockIdx.x * 256 + threadIdx.x;
    if (o >= 24*64*8*8) return;
    int x = o & 7, y = (o >> 3) & 7, ch = (o >> 6) & 63, img = o >> 12;
    float acc = bias[ch];
    const float* inb = g_c2 + (size_t)img * 12288;
    const float* wb  = w + ch * 48 * 9;
    for (int c = 0; c < 48; c++) {
        const float* in = inb + c * 256;
        const float* wp = wb + c * 9;
        #pragma unroll
        for (int kh = 0; kh < 3; kh++) {
            int iy = 2*y + kh; if (iy >= 16) continue;
            #pragma unroll
            for (int kw = 0; kw < 3; kw++) {
                int ix = 2*x + kw; if (ix >= 16) continue;
                acc += in[iy*16 + ix] * wp[kh*3 + kw];
            }
        }
    }
    g_c3[o] = fmaxf(acc, 0.f);
}

// ---------------- mean pool + logits: one block per image, 256 threads ----------------
__global__ void poollog_k(const float* __restrict__ Wlog, const float* __restrict__ blog) {
    __shared__ float pooled[64];
    int img = blockIdx.x, t = threadIdx.x;
    int ch = t >> 2, part = t & 3;
    const float* fp = g_c3 + (size_t)img * 4096 + ch * 64 + part * 16;
    float s = 0.f;
    #pragma unroll
    for (int i = 0; i < 16; i++) s += fp[i];
    s += __shfl_xor_sync(0xffffffff, s, 1);
    s += __shfl_xor_sync(0xffffffff, s, 2);
    if (part == 0) pooled[ch] = s * (1.f / 64.f);
    __syncthreads();
    if (t < 64) {
        float l = blog[t];
        #pragma unroll 8
        for (int cc = 0; cc < 64; cc++) l = fmaf(pooled[cc], Wlog[cc*64 + t], l);
        g_logits[img*64 + t] = l;
    }
}

// ---------------- u / v projections: one block per (img, p), 128 threads ----------------
__global__ void uv_k(const float* __restrict__ Wg1, const float* __restrict__ bg1) {
    __shared__ float a[66];
    int img = blockIdx.x >> 6;
    int p   = blockIdx.x & 63;
    int tid = threadIdx.x;
    if (tid < 64) a[tid] = g_c3[(size_t)img*4096 + tid*64 + p];
    if (tid == 64) a[64] = (float)(p >> 3) * 0.125f;   // ii[py]
    if (tid == 65) a[65] = (float)(p & 7)  * 0.125f;   // ii[px]
    __syncthreads();
    int n = tid; // 128
    float uacc = 0.f, vacc = bg1[n];
    for (int c = 0; c < 66; c++) {
        float av = a[c];
        uacc = fmaf(av, Wg1[c*128 + n],        uacc);
        vacc = fmaf(av, Wg1[(66 + c)*128 + n], vacc);
    }
    size_t off = (size_t)img * 8192 + p * 128 + n;
    g_u[off] = uacc;
    g_v[off] = vacc;
}

// ---------------- pair kernel: the 9.66 GFLOP core, FFMA2 (f32x2) packed ----------------
// One CTA per (b,j,i). smem: U[64][128], Vt[128][64], Wt[64][128], accT[64][256], bg2[64]
__global__ void __launch_bounds__(256, 1) pair_k(
    const float* __restrict__ Wg2, const float* __restrict__ bg2,
    const float* __restrict__ Wf1, const float* __restrict__ bf1,
    const float* __restrict__ Wf2, const float* __restrict__ bf2) {
    extern __shared__ float sm[];
    float* U    = sm;               // 8192
    float* Vt   = sm + 8192;        // 8192  Vt[k][q]
    float* Wt   = sm + 16384;       // 8192  Wt[n][k]  (16B aligned rows)
    float* accT = sm + 24576;       // 16384 accT[n][tid]
    float* bg2s = sm + 40960;       // 64

    int tid = threadIdx.x;
    int blk = blockIdx.x;
    int b = blk / 36; int r = blk - b*36; int j = r / 6; int i = r - j*6;
    const float* up = g_u + (size_t)(b*6 + i) * 8192;
    const float* vp = g_v + (size_t)(b*6 + j) * 8192;

    for (int idx = tid; idx < 8192; idx += 256) {
        U[idx] = up[idx];
        int q = idx >> 7, k = idx & 127;
        Vt[k*64 + q] = vp[idx];
        int kk = idx >> 6, n = idx & 63;
        Wt[n*128 + kk] = Wg2[idx];
    }
    for (int idx = tid; idx < 16384; idx += 256) accT[idx] = 0.f;
    if (tid < 64) bg2s[tid] = bg2[tid];
    __syncthreads();

    int warp = tid >> 5, lane = tid & 31;
    for (int p = warp; p < 64; p += 8) {
        const float4* Up = (const float4*)(U + p*128);
        for (int qh = 0; qh < 2; ++qh) {
            int q = qh*32 + lane;
            // Build h as 64 packed f32x2 pairs (adjacent k lanes)
            unsigned long long h2[64];
            #pragma unroll
            for (int k4 = 0; k4 < 32; k4++) {
                float4 uu = Up[k4];
                float a0 = fmaxf(uu.x + Vt[(4*k4+0)*64 + q], 0.f);
                float a1 = fmaxf(uu.y + Vt[(4*k4+1)*64 + q], 0.f);
                float a2 = fmaxf(uu.z + Vt[(4*k4+2)*64 + q], 0.f);
                float a3 = fmaxf(uu.w + Vt[(4*k4+3)*64 + q], 0.f);
                h2[2*k4+0] = pack2(a0, a1);
                h2[2*k4+1] = pack2(a2, a3);
            }
            #pragma unroll 2
            for (int n = 0; n < 64; n++) {
                const ulonglong2* Wp = (const ulonglong2*)(Wt + n*128);
                unsigned long long c0 = pack2(bg2s[n], 0.f);
                unsigned long long c1 = 0ull;   // {0.f, 0.f}
                unsigned long long c2 = 0ull;
                unsigned long long c3 = 0ull;
                #pragma unroll
                for (int k4 = 0; k4 < 16; k4++) {
                    ulonglong2 w = Wp[k4];
                    c0 = fma2(h2[2*k4+0], w.x, c0);
                    c1 = fma2(h2[2*k4+1], w.y, c1);
                }
                #pragma unroll
                for (int k4 = 16; k4 < 32; k4++) {
                    ulonglong2 w = Wp[k4];
                    c2 = fma2(h2[2*k4+0], w.x, c2);
                    c3 = fma2(h2[2*k4+1], w.y, c3);
                }
                float x0, x1, y0, y1, z0, z1, w0, w1;
                unpack2(c0, x0, x1); unpack2(c1, y0, y1);
                unpack2(c2, z0, z1); unpack2(c3, w0, w1);
                float sv = ((x0 + x1) + (y0 + y1)) + ((z0 + z1) + (w0 + w1));
                accT[n*256 + tid] += fmaxf(sv, 0.f);
            }
        }
    }
    __syncthreads();

    // reduce accT -> x_f[64] (reuse U)
    if (tid < 64) {
        float s = 0.f;
        const float* ap = accT + tid*256;
        for (int t = 0; t < 256; t++) s += ap[t];
        U[tid] = s;
    }
    __syncthreads();
    if (tid < 16) {
        float s = bf1[tid];
        for (int c = 0; c < 64; c++) s = fmaf(U[c], Wf1[c*16 + tid], s);
        Vt[tid] = fmaxf(s, 0.f);
    }
    __syncthreads();
    if (tid == 0) {
        float s = bf2[0];
        for (int t = 0; t < 16; t++) s = fmaf(Vt[t], Wf2[t], s);
        g_score[blk] = 1.f / (1.f + __expf(-s));
    }
}

// ---------------- final losses: single block ----------------
__global__ void final_k(const int* __restrict__ sy, const int* __restrict__ qy,
                        float* __restrict__ out) {
    __shared__ float sP[144], sY[144], scls[24];
    __shared__ int slab[24];
    int tid = threadIdx.x;
    if (tid < 144) sP[tid] = g_score[tid];
    if (tid < 24) {
        int b = tid / 6, s = tid - b*6;
        slab[tid] = (s < 5) ? sy[b*5 + s] : qy[b];
    }
    __syncthreads();
    if (tid < 24) {
        const float* row = g_logits + tid*64;
        float m = row[0];
        for (int n = 1; n < 64; n++) m = fmaxf(m, row[n]);
        float se = 0.f;
        for (int n = 0; n < 64; n++) se += __expf(row[n] - m);
        float lse = m + __logf(se);
        scls[tid] = -(row[slab[tid]] - lse);
    }
    if (tid < 144) {
        int b = tid / 36, r = tid - b*36; int jj = r / 6, ii = r - jj*6;
        sY[tid] = (slab[b*6 + jj] == slab[b*6 + ii]) ? 1.f : 0.f;
    }
    __syncthreads();
    if (tid == 0) {
        float cls = 0.f;
        for (int r2 = 0; r2 < 24; r2++) cls += scls[r2];
        cls /= 24.f;
        float euc = 0.f;
        for (int t = 0; t < 144; t++) { float d = sP[t] - sY[t]; euc += d*d; }
        euc /= 144.f;
        float syml = 0.f;
        for (int b2 = 0; b2 < 4; b2++) {
            float s2 = 0.f, a2 = 0.f;
            for (int jj = 0; jj < 6; jj++)
                for (int ii = 0; ii < 6; ii++) {
                    float pa = sP[b2*36 + jj*6 + ii];
                    float pb = sP[b2*36 + ii*6 + jj];
                    float sv = 0.5f*(pa + pb), av = 0.5f*(pa - pb);
                    s2 += sv*sv; a2 += av*av;
                }
            float sn = sqrtf(s2), an = sqrtf(a2);
            syml += (sn - an) / (sn + an);
        }
        syml *= 0.25f;
        out[0] = cls;
        out[1] = euc - 0.1f * syml;
        out[2] = syml;
    }
}

// ---------------- launch ----------------
extern "C" void kernel_launch(void* const* d_in, const int* in_sizes, int n_in,
                              void* d_out, int out_size) {
    const float* sx   = (const float*)d_in[0];
    const int*   sy   = (const int*)  d_in[1];
    const float* qx   = (const float*)d_in[2];
    const int*   qy   = (const int*)  d_in[3];
    const float* k1   = (const float*)d_in[4];
    const float* bc1  = (const float*)d_in[5];
    const float* k2   = (const float*)d_in[6];
    const float* bc2  = (const float*)d_in[7];
    const float* k3   = (const float*)d_in[8];
    const float* bc3  = (const float*)d_in[9];
    const float* Wlog = (const float*)d_in[10];
    const float* blog = (const float*)d_in[11];
    const float* Wg1  = (const float*)d_in[12];
    const float* bg1  = (const float*)d_in[13];
    const float* Wg2  = (const float*)d_in[14];
    const float* bg2  = (const float*)d_in[15];
    const float* Wf1  = (const float*)d_in[16];
    const float* bf1  = (const float*)d_in[17];
    const float* Wf2  = (const float*)d_in[18];
    const float* bf2  = (const float*)d_in[19];
    float* out = (float*)d_out;

    const int pair_smem = (8192*3 + 16384 + 64) * sizeof(float); // 164096 B
    cudaFuncSetAttribute(pair_k, cudaFuncAttributeMaxDynamicSharedMemorySize, pair_smem);

    conv1_k<<<3072, 256>>>(sx, qx, k1, bc1);
    conv2_k<<<1152, 256>>>(k2, bc2);
    conv3_k<<< 384, 256>>>(k3, bc3);
    poollog_k<<<24, 256>>>(Wlog, blog);
    uv_k<<<1536, 128>>>(Wg1, bg1);
    pair_k<<<144, 256, pair_smem>>>(Wg2, bg2, Wf1, bf1, Wf2, bf2);
    final_k<<<1, 160>>>(sy, qy, out);
}